// round 9
// baseline (speedup 1.0000x reference)
#include <cuda_runtime.h>

// ---------------- problem constants ----------------
#define MM    128            // n_mels
#define FF    1025           // n_stft
#define FPc   1088           // padded F
#define SSTR  1104           // spec SMEM row stride: %32==16, %4==0
#define DSTR  144            // mel SMEM row stride: %32==16
#define D2STR 264            // diff2 row stride in floats (132 float2)
#define TT    1024
#define NITER 20
#define LRc   0.3f
#define MOMc  0.9f
#define INVc  (2.0f / 4096.0f)

#define ROWS  28             // rows per CTA (max)
#define NTHR  512
#define NCTA  147            // 146*28 + 8 = 4096, single wave on 148 SMs
#define NJ    34             // phase C steps: 34 * 32 f = 1088
#define NC4M  12             // float4 chunks per mel (48 k slots >= max width ~46)

// ---------------- persistent table scratch ----------------
__device__ float2        g_w01[FPc];       // (w0, w1) per bin; w1 = fb[f, i0+1] (may be 0)
__device__ unsigned char g_i0[FPc];        // clamped first mel index (<=126)
__device__ float4        g_csr4[NC4M*MM];  // chunk-major: g_csr4[c*MM+m] = fb[lo+4c..+3, m]
__device__ int           g_lo[MM];         // aligned lo (multiple of 4)
__device__ int           g_nc4[MM];        // chunks per mel (<= NC4M)

// ---------------- merged prep kernel ----------------
// blocks [0,272): per-f table (4 warps = 4 f per block)
// blocks [272,400): per-mel aligned CSR
__global__ void prep_kernel(const float* __restrict__ fb) {
    const int blk = blockIdx.x;
    if (blk < 272) {
        const int warp = threadIdx.x >> 5;
        const int lane = threadIdx.x & 31;
        const int f = blk * 4 + warp;
        if (f >= FF) {
            if (f < FPc && lane == 0) { g_w01[f] = make_float2(0.f, 0.f); g_i0[f] = 0; }
            return;
        }
        const float* fr = fb + f * MM;
        unsigned b0 = __ballot_sync(0xffffffffu, fr[lane]      > 0.f);
        unsigned b1 = __ballot_sync(0xffffffffu, fr[lane + 32] > 0.f);
        unsigned b2 = __ballot_sync(0xffffffffu, fr[lane + 64] > 0.f);
        unsigned b3 = __ballot_sync(0xffffffffu, fr[lane + 96] > 0.f);
        if (lane == 0) {
            int fm = b0 ? (__ffs(b0) - 1)
                   : b1 ? (32 + __ffs(b1) - 1)
                   : b2 ? (64 + __ffs(b2) - 1)
                   : b3 ? (96 + __ffs(b3) - 1) : -1;
            if (fm < 0) {
                g_w01[f] = make_float2(0.f, 0.f); g_i0[f] = 0;
            } else {
                int i0 = fm > 126 ? 126 : fm;       // weights read straight from fb -> exact
                g_w01[f] = make_float2(fr[i0], fr[i0 + 1]);
                g_i0[f]  = (unsigned char)i0;
            }
        }
    } else {
        __shared__ int s_mn[128], s_mx[128];
        const int m = blk - 272;
        const int t = threadIdx.x;
        int mn = FF, mx = -1;
        for (int f = t; f < FF; f += 128) {
            if (fb[f * MM + m] > 0.f) { mn = min(mn, f); mx = max(mx, f); }
        }
        s_mn[t] = mn; s_mx[t] = mx;
        __syncthreads();
        for (int s = 64; s > 0; s >>= 1) {
            if (t < s) { s_mn[t] = min(s_mn[t], s_mn[t + s]); s_mx[t] = max(s_mx[t], s_mx[t + s]); }
            __syncthreads();
        }
        const int lo_al = (s_mx[0] < 0) ? 0 : (s_mn[0] & ~3);
        int cnt = (s_mx[0] < 0) ? 0 : (s_mx[0] + 1 - lo_al);
        int cnt_al = (cnt + 3) & ~3;
        if (cnt_al > 4 * NC4M) cnt_al = 4 * NC4M;   // structurally impossible; safety
        if (t == 0) { g_lo[m] = lo_al; g_nc4[m] = cnt_al >> 2; }
        if (t < 4 * NC4M) {
            // fb is zero outside [mn,mx], so unconditional reads are exact
            float w = (lo_al + t < FF) ? fb[(lo_al + t) * MM + m] : 0.f;
            reinterpret_cast<float*>(g_csr4)[((t >> 2) * MM + m) * 4 + (t & 3)] = w;
        }
    }
}

// ---------------- SMEM layout (floats) ----------------
#define OFF_SPEC 0
#define OFF_MEL  (OFF_SPEC + ROWS * SSTR)          // 30912
#define OFF_D2   (OFF_MEL  + ROWS * DSTR)          // 34944
#define OFF_W01  (OFF_D2   + ROWS * D2STR)         // 42336 (16B aligned)
#define OFF_CSR  (OFF_W01  + 2 * FPc)              // 44512 (16B aligned)
#define OFF_LO   (OFF_CSR  + 4 * NC4M * MM)        // 50656
#define OFF_NC   (OFF_LO   + MM)                   // 50784
#define OFF_I0   (OFF_NC   + MM)                   // 50912
#define SM_FLOATS (OFF_I0 + FPc / 4)               // 51184 floats = 204736 B

// ---------------- main persistent kernel ----------------
__global__ __launch_bounds__(NTHR, 1)
void invmel_kernel(const float* __restrict__ melspec,
                   const float* __restrict__ spec_init,
                   float* __restrict__ out) {
    extern __shared__ float smem[];
    float*  s_spec  = smem + OFF_SPEC;
    float*  s_mel   = smem + OFF_MEL;
    float*  s_d2f   = smem + OFF_D2;                        // diff pairs, float view
    float2* s_d2    = reinterpret_cast<float2*>(s_d2f);     // float2 view
    float*  s_w01f  = smem + OFF_W01;
    float4* s_csr4  = reinterpret_cast<float4*>(smem + OFF_CSR);
    int*    s_lo    = reinterpret_cast<int*>(smem + OFF_LO);
    int*    s_nc    = reinterpret_cast<int*>(smem + OFF_NC);
    unsigned char* s_i0 = reinterpret_cast<unsigned char*>(smem + OFF_I0);

    const int tid   = threadIdx.x;
    const int row0  = blockIdx.x * ROWS;
    const int nrows = min(ROWS, 4096 - row0);     // 28, or 8 for last CTA

    // ---- tables ----
    for (int i = tid; i < FPc; i += NTHR) {
        reinterpret_cast<float2*>(s_w01f)[i] = g_w01[i];
        s_i0[i] = g_i0[i];
    }
    for (int i = tid; i < NC4M * MM; i += NTHR) s_csr4[i] = g_csr4[i];
    if (tid < MM) { s_lo[tid] = g_lo[tid]; s_nc[tid] = g_nc4[tid]; }

    // ---- zero diff2 (slot [127].y = d[128] pad stays 0 forever) ----
    for (int i = tid; i < ROWS * D2STR; i += NTHR) s_d2f[i] = 0.f;

    // ---- spec tile (coalesced over f; pad [FF,FPc) with 0) ----
    for (int i = tid; i < nrows * FPc; i += NTHR) {
        const int r = i / FPc;
        const int f = i - r * FPc;
        s_spec[r * SSTR + f] = (f < FF) ? spec_init[(size_t)(row0 + r) * FF + f] : 0.f;
    }
    // ---- mel tile: s_mel[r][m] = melspec[b_r][m][t_r] (r fastest for coalescing) ----
    for (int i = tid; i < nrows * MM; i += NTHR) {
        const int m = i / nrows;
        const int r = i - m * nrows;
        const int g = row0 + r;
        const int b = g >> 10;
        const int t = g & 1023;
        s_mel[r * DSTR + m] = melspec[((size_t)b * MM + m) * TT + t];
    }
    __syncthreads();

    // ---- roles: all work for row r is done by half-warp r -> warp-local loop ----
    const int row    = tid >> 4;   // 0..31
    const int q      = tid & 15;   // 0..15
    const int sbase  = row * SSTR;
    const int dbase  = row * DSTR;
    const int d2base = row * (D2STR / 2);   // float2 units
    const bool active = (row < nrows);      // warp-uniform (nrows even)

    // hoisted per-mel metadata (iteration-invariant)
    int lo8[8], nc8[8];
    #pragma unroll
    for (int j = 0; j < 8; ++j) {
        const int m = 16 * j + q;
        lo8[j] = s_lo[m];
        nc8[j] = s_nc[m];
    }

    float2 buf[NJ];
    #pragma unroll
    for (int j = 0; j < NJ; ++j) buf[j] = make_float2(0.f, 0.f);

    for (int it = 0; it < NITER; ++it) {
        // ======== phase A: d[m] = mel[m] - sum_k w(m,k)*spec[lo+k]; write pair slots ========
        if (active) {
            #pragma unroll
            for (int j = 0; j < 8; ++j) {
                const int m = 16 * j + q;
                const float4* __restrict__ cw  = s_csr4 + m;
                const float4* __restrict__ sp4 = reinterpret_cast<const float4*>(s_spec + sbase + lo8[j]);
                float a0 = 0.f, a1 = 0.f;
                const int n = nc8[j];
                #pragma unroll 2
                for (int c = 0; c < n; ++c) {
                    const float4 w = cw[c * MM];
                    const float4 s = sp4[c];
                    a0 = fmaf(w.x, s.x, a0);
                    a1 = fmaf(w.y, s.y, a1);
                    a0 = fmaf(w.z, s.z, a0);
                    a1 = fmaf(w.w, s.w, a1);
                }
                const float d = s_mel[dbase + m] - (a0 + a1);
                float* __restrict__ df = s_d2f + row * D2STR;
                df[2 * m] = d;               // diff2[m].x = d[m]
                if (m) df[2 * m - 1] = d;    // diff2[m-1].y = d[m]
            }
        }
        __syncwarp();

        // ======== phase C: dot = w0*d[i0] + w1*d[i0+1]; momentum; clamp ========
        if (active) {
            #pragma unroll
            for (int j = 0; j < NJ; ++j) {
                const int f = 32 * j + 2 * q;
                const float4 w = *reinterpret_cast<const float4*>(s_w01f + 2 * f); // (w0a,w1a,w0b,w1b)
                const uchar2 ii = *reinterpret_cast<const uchar2*>(s_i0 + f);
                const float2 dA = s_d2[d2base + ii.x];
                const float2 dB = s_d2[d2base + ii.y];
                const float dota = fmaf(w.x, dA.x, w.y * dA.y);
                const float dotb = fmaf(w.z, dB.x, w.w * dB.y);
                float2 bv;
                bv.x = fmaf(MOMc, buf[j].x, -INVc * dota);
                bv.y = fmaf(MOMc, buf[j].y, -INVc * dotb);
                buf[j] = bv;
                float2 sp = *reinterpret_cast<const float2*>(s_spec + sbase + f);
                sp.x = fmaxf(fmaf(-LRc, bv.x, sp.x), 0.f);
                sp.y = fmaxf(fmaf(-LRc, bv.y, sp.y), 0.f);
                *reinterpret_cast<float2*>(s_spec + sbase + f) = sp;
            }
        }
        __syncwarp();
    }
    __syncthreads();

    // ---- epilogue: out[b][f][t] = spec[r][f]; 4-row float4 groups (batch-pure) ----
    for (int f = tid; f < FF; f += NTHR) {
        const float* __restrict__ spp = s_spec + f;
        #pragma unroll 2
        for (int r = 0; r < nrows; r += 4) {
            const int g = row0 + r;           // multiple of 4; group shares batch
            const int b = g >> 10;
            const int t = g & 1023;
            float4 v;
            v.x = spp[(r + 0) * SSTR];
            v.y = spp[(r + 1) * SSTR];
            v.z = spp[(r + 2) * SSTR];
            v.w = spp[(r + 3) * SSTR];
            *reinterpret_cast<float4*>(out + ((size_t)b * FF + f) * TT + t) = v;
        }
    }
}

// ---------------- launch ----------------
extern "C" void kernel_launch(void* const* d_in, const int* in_sizes, int n_in,
                              void* d_out, int out_size) {
    const float* melspec   = (const float*)d_in[0];  // (4,128,1024)
    const float* spec_init = (const float*)d_in[1];  // (4,1024,1025)
    const float* fb        = (const float*)d_in[2];  // (1025,128)
    float* out             = (float*)d_out;          // (4,1025,1024)

    const int smem_bytes = SM_FLOATS * sizeof(float);   // 204736
    cudaFuncSetAttribute(invmel_kernel, cudaFuncAttributeMaxDynamicSharedMemorySize, smem_bytes);

    prep_kernel<<<400, 128>>>(fb);
    invmel_kernel<<<NCTA, NTHR, smem_bytes>>>(melspec, spec_init, out);
}

// round 10
// speedup vs baseline: 1.1033x; 1.1033x over previous
#include <cuda_runtime.h>
#include <cuda_fp16.h>

// ---------------- problem constants ----------------
#define MM    128            // n_mels
#define FF    1025           // n_stft
#define FPc   1088           // padded F
#define SSTR  1104           // spec SMEM row stride: %32==16, %4==0
#define DSTR  144            // mel SMEM row stride
#define D2STR 264            // diff2 row stride in floats (132 float2)
#define TT    1024
#define NITER 20
#define LRc   0.3f
#define MOMc  0.9f
#define INVc  (2.0f / 4096.0f)

#define ROWS  28             // rows per CTA (max)
#define NTHR  512
#define NCTA  147            // 146*28 + 8 = 4096, single wave
#define NJ    17             // phase C steps: 17 * 64 f = 1088
#define NC4M  12             // 4-slot chunks per mel (48 k slots >= max width ~46)

// ---------------- persistent table scratch ----------------
__device__ __half2 g_w01h[FPc];        // (w0, w1) per bin, fp16
__device__ unsigned char g_i0[FPc];    // clamped first mel index (<=126)
__device__ uint2   g_csrh[NC4M*MM];    // chunk-major: 4 fp16 weights per chunk per mel
__device__ int     g_lo[MM];           // aligned lo (multiple of 4)
__device__ int     g_nc4[MM];          // chunks per mel (<= NC4M)

// ---------------- merged prep kernel ----------------
__global__ void prep_kernel(const float* __restrict__ fb) {
    const int blk = blockIdx.x;
    if (blk < 272) {
        const int warp = threadIdx.x >> 5;
        const int lane = threadIdx.x & 31;
        const int f = blk * 4 + warp;
        if (f >= FF) {
            if (f < FPc && lane == 0) { g_w01h[f] = __floats2half2_rn(0.f, 0.f); g_i0[f] = 0; }
            return;
        }
        const float* fr = fb + f * MM;
        unsigned b0 = __ballot_sync(0xffffffffu, fr[lane]      > 0.f);
        unsigned b1 = __ballot_sync(0xffffffffu, fr[lane + 32] > 0.f);
        unsigned b2 = __ballot_sync(0xffffffffu, fr[lane + 64] > 0.f);
        unsigned b3 = __ballot_sync(0xffffffffu, fr[lane + 96] > 0.f);
        if (lane == 0) {
            int fm = b0 ? (__ffs(b0) - 1)
                   : b1 ? (32 + __ffs(b1) - 1)
                   : b2 ? (64 + __ffs(b2) - 1)
                   : b3 ? (96 + __ffs(b3) - 1) : -1;
            if (fm < 0) {
                g_w01h[f] = __floats2half2_rn(0.f, 0.f); g_i0[f] = 0;
            } else {
                int i0 = fm > 126 ? 126 : fm;
                g_w01h[f] = __floats2half2_rn(fr[i0], fr[i0 + 1]);
                g_i0[f]   = (unsigned char)i0;
            }
        }
    } else {
        __shared__ int s_mn[128], s_mx[128];
        const int m = blk - 272;
        const int t = threadIdx.x;
        int mn = FF, mx = -1;
        for (int f = t; f < FF; f += 128) {
            if (fb[f * MM + m] > 0.f) { mn = min(mn, f); mx = max(mx, f); }
        }
        s_mn[t] = mn; s_mx[t] = mx;
        __syncthreads();
        for (int s = 64; s > 0; s >>= 1) {
            if (t < s) { s_mn[t] = min(s_mn[t], s_mn[t + s]); s_mx[t] = max(s_mx[t], s_mx[t + s]); }
            __syncthreads();
        }
        const int lo_al = (s_mx[0] < 0) ? 0 : (s_mn[0] & ~3);
        int cnt = (s_mx[0] < 0) ? 0 : (s_mx[0] + 1 - lo_al);
        int cnt_al = (cnt + 3) & ~3;
        if (cnt_al > 4 * NC4M) cnt_al = 4 * NC4M;
        if (t == 0) { g_lo[m] = lo_al; g_nc4[m] = cnt_al >> 2; }
        if (t < 4 * NC4M) {
            float w = (lo_al + t < FF) ? fb[(lo_al + t) * MM + m] : 0.f;
            reinterpret_cast<__half*>(g_csrh)[((t >> 2) * MM + m) * 4 + (t & 3)] = __float2half(w);
        }
    }
}

// ---------------- SMEM layout (floats) ----------------
#define OFF_SPEC 0
#define OFF_MEL  (OFF_SPEC + ROWS * SSTR)          // 30912
#define OFF_D2   (OFF_MEL  + ROWS * DSTR)          // 34944
#define OFF_W01H (OFF_D2   + ROWS * D2STR)         // 42336 (16B aligned)
#define OFF_CSR  (OFF_W01H + FPc)                  // 43424 (8B aligned)
#define OFF_LO   (OFF_CSR  + 2 * NC4M * MM)        // 46496
#define OFF_NC   (OFF_LO   + MM)                   // 46624
#define OFF_I0   (OFF_NC   + MM)                   // 46752
#define SM_FLOATS (OFF_I0 + FPc / 4)               // 47024 floats = 188096 B

// ---------------- main persistent kernel ----------------
__global__ __launch_bounds__(NTHR, 1)
void invmel_kernel(const float* __restrict__ melspec,
                   const float* __restrict__ spec_init,
                   float* __restrict__ out) {
    extern __shared__ float smem[];
    float*  s_spec  = smem + OFF_SPEC;
    float*  s_mel   = smem + OFF_MEL;
    float*  s_d2f   = smem + OFF_D2;
    float2* s_d2    = reinterpret_cast<float2*>(s_d2f);
    unsigned int* s_w01h = reinterpret_cast<unsigned int*>(smem + OFF_W01H); // half2 per f
    uint2*  s_csr2  = reinterpret_cast<uint2*>(smem + OFF_CSR);              // half4 per chunk
    int*    s_lo    = reinterpret_cast<int*>(smem + OFF_LO);
    int*    s_nc    = reinterpret_cast<int*>(smem + OFF_NC);
    unsigned char* s_i0 = reinterpret_cast<unsigned char*>(smem + OFF_I0);

    const int tid   = threadIdx.x;
    const int row0  = blockIdx.x * ROWS;
    const int nrows = min(ROWS, 4096 - row0);     // 28, or 8 for last CTA

    // ---- tables ----
    for (int i = tid; i < FPc; i += NTHR) {
        s_w01h[i] = reinterpret_cast<const unsigned int*>(g_w01h)[i];
        s_i0[i]   = g_i0[i];
    }
    for (int i = tid; i < NC4M * MM; i += NTHR) s_csr2[i] = g_csrh[i];
    if (tid < MM) { s_lo[tid] = g_lo[tid]; s_nc[tid] = g_nc4[tid]; }

    // ---- zero diff2 ----
    for (int i = tid; i < ROWS * D2STR; i += NTHR) s_d2f[i] = 0.f;

    // ---- spec tile ----
    for (int i = tid; i < nrows * FPc; i += NTHR) {
        const int r = i / FPc;
        const int f = i - r * FPc;
        s_spec[r * SSTR + f] = (f < FF) ? spec_init[(size_t)(row0 + r) * FF + f] : 0.f;
    }
    // ---- mel tile ----
    for (int i = tid; i < nrows * MM; i += NTHR) {
        const int m = i / nrows;
        const int r = i - m * nrows;
        const int g = row0 + r;
        const int b = g >> 10;
        const int t = g & 1023;
        s_mel[r * DSTR + m] = melspec[((size_t)b * MM + m) * TT + t];
    }
    __syncthreads();

    // ---- roles: half-warp per row; warp-local loop ----
    const int row    = tid >> 4;
    const int q      = tid & 15;
    const int sbase  = row * SSTR;
    const int dbase  = row * DSTR;
    const int d2base = row * (D2STR / 2);
    const bool active = (row < nrows);            // warp-uniform (nrows even)

    // packed per-mel metadata (lo | nc<<16)
    int lonc[8];
    #pragma unroll
    for (int j = 0; j < 8; ++j) {
        const int m = 16 * j + q;
        lonc[j] = s_lo[m] | (s_nc[m] << 16);
    }

    float4 buf[NJ];
    #pragma unroll
    for (int j = 0; j < NJ; ++j) buf[j] = make_float4(0.f, 0.f, 0.f, 0.f);

    for (int it = 0; it < NITER; ++it) {
        // ======== phase A: d[m] = mel[m] - sum_k w(m,k)*spec[lo+k] ========
        if (active) {
            #pragma unroll
            for (int j = 0; j < 8; ++j) {
                const int m  = 16 * j + q;
                const int lo = lonc[j] & 0xffff;
                const int n  = lonc[j] >> 16;
                const uint2* __restrict__ cw  = s_csr2 + m;
                const float4* __restrict__ sp4 = reinterpret_cast<const float4*>(s_spec + sbase + lo);
                float a0 = 0.f, a1 = 0.f;
                #pragma unroll 2
                for (int c = 0; c < n; ++c) {
                    const uint2 wr = cw[c * MM];
                    const float2 w0 = __half22float2(*reinterpret_cast<const __half2*>(&wr.x));
                    const float2 w1 = __half22float2(*reinterpret_cast<const __half2*>(&wr.y));
                    const float4 s = sp4[c];
                    a0 = fmaf(w0.x, s.x, a0);
                    a1 = fmaf(w0.y, s.y, a1);
                    a0 = fmaf(w1.x, s.z, a0);
                    a1 = fmaf(w1.y, s.w, a1);
                }
                float d = s_mel[dbase + m] - (a0 + a1);
                // neighbor's d via shuffle (warp-uniform active mask)
                float dn = __shfl_down_sync(0xffffffffu, d, 1);
                if (j == 7 && q == 15) dn = 0.f;            // d[128] pad
                *reinterpret_cast<float2*>(s_d2f + row * D2STR + 2 * m) = make_float2(d, dn);
                // fix previous group's q=15 slot (its shuffled dn was cross-row garbage)
                if (j > 0 && q == 0)
                    s_d2f[row * D2STR + 2 * m - 1] = d;     // d2[16j-1].y = d[16j]
            }
        }
        __syncwarp();

        // ======== phase C: 4 consecutive f per lane; dot = w0*d0 + w1*d1 ========
        if (active) {
            #pragma unroll
            for (int j = 0; j < NJ; ++j) {
                const int f = 64 * j + 4 * q;
                const uint4 wr = *reinterpret_cast<const uint4*>(s_w01h + f);     // 4 half2
                const uchar4 ii = *reinterpret_cast<const uchar4*>(s_i0 + f);
                float4 sp = *reinterpret_cast<const float4*>(s_spec + sbase + f);
                const float2 wA = __half22float2(*reinterpret_cast<const __half2*>(&wr.x));
                const float2 wB = __half22float2(*reinterpret_cast<const __half2*>(&wr.y));
                const float2 wC = __half22float2(*reinterpret_cast<const __half2*>(&wr.z));
                const float2 wD = __half22float2(*reinterpret_cast<const __half2*>(&wr.w));
                const float2 dA = s_d2[d2base + ii.x];
                const float2 dB = s_d2[d2base + ii.y];
                const float2 dC = s_d2[d2base + ii.z];
                const float2 dD = s_d2[d2base + ii.w];
                const float dot0 = fmaf(wA.x, dA.x, wA.y * dA.y);
                const float dot1 = fmaf(wB.x, dB.x, wB.y * dB.y);
                const float dot2 = fmaf(wC.x, dC.x, wC.y * dC.y);
                const float dot3 = fmaf(wD.x, dD.x, wD.y * dD.y);
                float4 bv;
                bv.x = fmaf(MOMc, buf[j].x, -INVc * dot0);
                bv.y = fmaf(MOMc, buf[j].y, -INVc * dot1);
                bv.z = fmaf(MOMc, buf[j].z, -INVc * dot2);
                bv.w = fmaf(MOMc, buf[j].w, -INVc * dot3);
                buf[j] = bv;
                sp.x = fmaxf(fmaf(-LRc, bv.x, sp.x), 0.f);
                sp.y = fmaxf(fmaf(-LRc, bv.y, sp.y), 0.f);
                sp.z = fmaxf(fmaf(-LRc, bv.z, sp.z), 0.f);
                sp.w = fmaxf(fmaf(-LRc, bv.w, sp.w), 0.f);
                *reinterpret_cast<float4*>(s_spec + sbase + f) = sp;
            }
        }
        __syncwarp();
    }
    __syncthreads();

    // ---- epilogue: out[b][f][t] = spec[r][f]; 4-row float4 groups ----
    for (int f = tid; f < FF; f += NTHR) {
        const float* __restrict__ spp = s_spec + f;
        #pragma unroll 2
        for (int r = 0; r < nrows; r += 4) {
            const int g = row0 + r;
            const int b = g >> 10;
            const int t = g & 1023;
            float4 v;
            v.x = spp[(r + 0) * SSTR];
            v.y = spp[(r + 1) * SSTR];
            v.z = spp[(r + 2) * SSTR];
            v.w = spp[(r + 3) * SSTR];
            *reinterpret_cast<float4*>(out + ((size_t)b * FF + f) * TT + t) = v;
        }
    }
}

// ---------------- launch ----------------
extern "C" void kernel_launch(void* const* d_in, const int* in_sizes, int n_in,
                              void* d_out, int out_size) {
    const float* melspec   = (const float*)d_in[0];  // (4,128,1024)
    const float* spec_init = (const float*)d_in[1];  // (4,1024,1025)
    const float* fb        = (const float*)d_in[2];  // (1025,128)
    float* out             = (float*)d_out;          // (4,1025,1024)

    const int smem_bytes = SM_FLOATS * sizeof(float);   // 188096
    cudaFuncSetAttribute(invmel_kernel, cudaFuncAttributeMaxDynamicSharedMemorySize, smem_bytes);

    prep_kernel<<<400, 128>>>(fb);
    invmel_kernel<<<NCTA, NTHR, smem_bytes>>>(melspec, spec_init, out);
}